// round 1
// baseline (speedup 1.0000x reference)
#include <cuda_runtime.h>
#include <math.h>

#define BATCH 4096
#define SQ    64
#define DM    256
#define NH    8
#define HDIM  32
#define FFD   1024
#define NL    6
#define MTOK  (BATCH*SQ)   /* 262144 */

// ---------------- scratch (no allocations allowed) ----------------
__device__ float g_x[MTOK*DM];          // 268MB  activations [B*64, 256]
__device__ float g_qkv[MTOK*3*DM];      // 805MB  qkv          [B*64, 768]
__device__ float g_o[MTOK*DM];          // attn output
__device__ float g_y[MTOK*DM];          // sublayer output
__device__ float g_ffb[MTOK*FFD];       // 1.07GB ff hidden
__device__ float g_pe[SQ*DM];
__device__ float g_pooled[BATCH*DM];
__device__ float g_vh[BATCH*DM];
__device__ float g_ch[BATCH*DM];
__device__ float g_h1[BATCH*1024];

// ---------------- PE precompute ----------------
__global__ void pe_kernel(float* __restrict__ pe) {
    int s = blockIdx.x, d = threadIdx.x;
    int row = s >> 3, col = s & 7;
    int m = d >> 1;
    float div = powf(10000.0f, (2.0f * (float)m) / 256.0f);
    float v = (d & 1) ? cosf((float)col / div) : sinf((float)row / div);
    pe[s * DM + d] = v;
}

// ---------------- tokens + embedding + PE ----------------
__global__ void embed_kernel(const float* __restrict__ board,
                             const float* __restrict__ emb,
                             const float* __restrict__ pe,
                             float* __restrict__ x) {
    int tokidx = blockIdx.x;          // b*64 + s
    int b = tokidx >> 6, s = tokidx & 63;
    __shared__ float ch[14];
    __shared__ int tok;
    int d = threadIdx.x;              // 256 threads
    if (d < 14) ch[d] = board[(size_t)b * 896 + (size_t)d * 64 + s];
    __syncthreads();
    if (d == 0) {
        float mx = ch[0]; int idx = 0;
        #pragma unroll
        for (int c = 1; c < 14; c++) { if (ch[c] > mx) { mx = ch[c]; idx = c; } }
        tok = (mx > 0.0f) ? (idx + 1) : 0;
    }
    __syncthreads();
    x[(size_t)tokidx * DM + d] = emb[tok * DM + d] + pe[s * DM + d];
}

// ---------------- generic SGEMM: C[M,N] = A[M,K] @ W[N,K]^T + bias (+relu) ----
// BM=BN=128, BK=16, 256 threads, 8x8 per thread.
__global__ __launch_bounds__(256) void sgemm_nt(
    const float* __restrict__ A, const float* __restrict__ W,
    const float* __restrict__ bias, float* __restrict__ C,
    int M, int N, int K, int relu)
{
    __shared__ float As[16][132];
    __shared__ float Ws[16][132];
    int tid = threadIdx.x;
    int tx = tid & 15, ty = tid >> 4;
    int bn = blockIdx.x * 128;
    int bm = blockIdx.y * 128;

    float acc[8][8];
    #pragma unroll
    for (int i = 0; i < 8; i++)
        #pragma unroll
        for (int j = 0; j < 8; j++) acc[i][j] = 0.0f;

    for (int k0 = 0; k0 < K; k0 += 16) {
        #pragma unroll
        for (int i = 0; i < 8; i++) {
            int lin = tid + 256 * i;       // 0..2047
            int m = lin >> 4, kk = lin & 15;
            As[kk][m] = A[(size_t)(bm + m) * K + k0 + kk];
            Ws[kk][m] = W[(size_t)(bn + m) * K + k0 + kk];
        }
        __syncthreads();
        #pragma unroll
        for (int kk = 0; kk < 16; kk++) {
            float4 a0 = *(const float4*)&As[kk][ty * 8];
            float4 a1 = *(const float4*)&As[kk][ty * 8 + 4];
            float4 w0 = *(const float4*)&Ws[kk][tx * 4];
            float4 w1 = *(const float4*)&Ws[kk][64 + tx * 4];
            float a[8] = {a0.x, a0.y, a0.z, a0.w, a1.x, a1.y, a1.z, a1.w};
            float w[8] = {w0.x, w0.y, w0.z, w0.w, w1.x, w1.y, w1.z, w1.w};
            #pragma unroll
            for (int i = 0; i < 8; i++)
                #pragma unroll
                for (int j = 0; j < 8; j++)
                    acc[i][j] = fmaf(a[i], w[j], acc[i][j]);
        }
        __syncthreads();
    }

    float bs[8];
    #pragma unroll
    for (int j = 0; j < 4; j++) {
        bs[j]     = bias ? bias[bn + tx * 4 + j]      : 0.0f;
        bs[4 + j] = bias ? bias[bn + 64 + tx * 4 + j] : 0.0f;
    }
    #pragma unroll
    for (int i = 0; i < 8; i++) {
        int m = bm + ty * 8 + i;
        float r[8];
        #pragma unroll
        for (int j = 0; j < 8; j++) {
            float v = acc[i][j] + bs[j];
            if (relu) v = fmaxf(v, 0.0f);
            r[j] = v;
        }
        *(float4*)&C[(size_t)m * N + bn + tx * 4]      = make_float4(r[0], r[1], r[2], r[3]);
        *(float4*)&C[(size_t)m * N + bn + 64 + tx * 4] = make_float4(r[4], r[5], r[6], r[7]);
    }
}

// ---------------- attention: one CTA per (b, h) ----------------
__global__ __launch_bounds__(256) void attn_kernel(const float* __restrict__ qkv,
                                                   float* __restrict__ o) {
    int bh = blockIdx.x;
    int b = bh >> 3, h = bh & 7;
    __shared__ float qs[64][33];
    __shared__ float ks[64][33];
    __shared__ float vs[64][33];
    __shared__ float sc[64][65];
    int tid = threadIdx.x;

    for (int t = tid; t < 64 * 32; t += 256) {
        int row = t >> 5, d = t & 31;
        size_t base = ((size_t)b * 64 + row) * 768;
        qs[row][d] = qkv[base + h * 32 + d];
        ks[row][d] = qkv[base + 256 + h * 32 + d];
        vs[row][d] = qkv[base + 512 + h * 32 + d];
    }
    __syncthreads();

    const float scale = 0.17677669529663687f;  // 1/sqrt(32)
    for (int t = tid; t < 4096; t += 256) {
        int i = t >> 6, j = t & 63;
        float acc = 0.0f;
        #pragma unroll
        for (int d = 0; d < 32; d++) acc = fmaf(qs[i][d], ks[j][d], acc);
        sc[i][j] = acc * scale;
    }
    __syncthreads();

    if (tid < 64) {
        float mx = -1e30f;
        #pragma unroll 8
        for (int j = 0; j < 64; j++) mx = fmaxf(mx, sc[tid][j]);
        float sum = 0.0f;
        #pragma unroll 8
        for (int j = 0; j < 64; j++) { float e = expf(sc[tid][j] - mx); sc[tid][j] = e; sum += e; }
        float inv = 1.0f / sum;
        #pragma unroll 8
        for (int j = 0; j < 64; j++) sc[tid][j] *= inv;
    }
    __syncthreads();

    for (int t = tid; t < 2048; t += 256) {
        int i = t >> 5, d = t & 31;
        float acc = 0.0f;
        #pragma unroll 8
        for (int j = 0; j < 64; j++) acc = fmaf(sc[i][j], vs[j][d], acc);
        o[((size_t)b * 64 + i) * DM + h * 32 + d] = acc;
    }
}

// ---------------- residual + layernorm (row-wise) ----------------
__global__ __launch_bounds__(256) void add_ln_kernel(float* __restrict__ x,
                                                     const float* __restrict__ y,
                                                     const float* __restrict__ gg,
                                                     const float* __restrict__ bb) {
    size_t base = (size_t)blockIdx.x * 256;
    int d = threadIdx.x;
    float t = x[base + d] + y[base + d];
    __shared__ float red[8];
    __shared__ float stat;
    float s = t;
    #pragma unroll
    for (int off = 16; off; off >>= 1) s += __shfl_xor_sync(0xffffffffu, s, off);
    if ((d & 31) == 0) red[d >> 5] = s;
    __syncthreads();
    if (d == 0) { float m = 0; for (int i = 0; i < 8; i++) m += red[i]; stat = m * (1.0f / 256.0f); }
    __syncthreads();
    float mean = stat;
    float c = t - mean;
    s = c * c;
    #pragma unroll
    for (int off = 16; off; off >>= 1) s += __shfl_xor_sync(0xffffffffu, s, off);
    __syncthreads();
    if ((d & 31) == 0) red[d >> 5] = s;
    __syncthreads();
    if (d == 0) { float v = 0; for (int i = 0; i < 8; i++) v += red[i]; stat = rsqrtf(v * (1.0f / 256.0f) + 1e-5f); }
    __syncthreads();
    x[base + d] = c * stat * gg[d] + bb[d];
}

// ---------------- mean pooling over the 64 squares ----------------
__global__ void pool_kernel(const float* __restrict__ x, float* __restrict__ pooled) {
    int b = blockIdx.x, d = threadIdx.x;
    float s = 0.0f;
    #pragma unroll 8
    for (int i = 0; i < 64; i++) s += x[((size_t)b * 64 + i) * DM + d];
    pooled[(size_t)b * DM + d] = s * (1.0f / 64.0f);
}

// ---------------- tiny head finals (value / classification) ----------------
__global__ void head_final_kernel(const float* __restrict__ hid,
                                  const float* __restrict__ w,
                                  const float* __restrict__ bias,
                                  float* __restrict__ out, int nout, int do_tanh) {
    int b = blockIdx.x;
    int lane = threadIdx.x;  // 32 threads
    for (int o = 0; o < nout; o++) {
        float s = 0.0f;
        #pragma unroll
        for (int i = lane; i < 256; i += 32) s = fmaf(hid[(size_t)b * 256 + i], w[o * 256 + i], s);
        #pragma unroll
        for (int off = 16; off; off >>= 1) s += __shfl_xor_sync(0xffffffffu, s, off);
        if (lane == 0) {
            float v = s + bias[o];
            out[(size_t)b * nout + o] = do_tanh ? tanhf(v) : v;
        }
    }
}

// ---------------- host side ----------------
static inline void sgemm(const float* A, const float* W, const float* bias, float* C,
                         int M, int N, int K, int relu) {
    dim3 g(N / 128, M / 128), blk(256);
    sgemm_nt<<<g, blk>>>(A, W, bias, C, M, N, K, relu);
}

extern "C" void kernel_launch(void* const* d_in, const int* in_sizes, int n_in,
                              void* d_out, int out_size) {
    const float* board = (const float*)d_in[0];
    const float* emb   = (const float*)d_in[1];
    const float* qkv_w = (const float*)d_in[2];
    const float* qkv_b = (const float*)d_in[3];
    const float* out_w = (const float*)d_in[4];
    const float* out_b = (const float*)d_in[5];
    const float* ln1_g = (const float*)d_in[6];
    const float* ln1_b = (const float*)d_in[7];
    const float* ln2_g = (const float*)d_in[8];
    const float* ln2_b = (const float*)d_in[9];
    const float* ff1_w = (const float*)d_in[10];
    const float* ff1_b = (const float*)d_in[11];
    const float* ff2_w = (const float*)d_in[12];
    const float* ff2_b = (const float*)d_in[13];
    const float* vw1 = (const float*)d_in[14];
    const float* vb1 = (const float*)d_in[15];
    const float* vw2 = (const float*)d_in[16];
    const float* vb2 = (const float*)d_in[17];
    const float* pw1 = (const float*)d_in[18];
    const float* pb1 = (const float*)d_in[19];
    const float* pw2 = (const float*)d_in[20];
    const float* pb2 = (const float*)d_in[21];
    const float* cw1 = (const float*)d_in[22];
    const float* cb1 = (const float*)d_in[23];
    const float* cw2 = (const float*)d_in[24];
    const float* cb2 = (const float*)d_in[25];

    float* out = (float*)d_out;
    float* out_value  = out;                                  // [4096, 1]
    float* out_policy = out + BATCH;                          // [4096, 4096]
    float* out_class  = out + BATCH + (size_t)BATCH * 4096;   // [4096, 3]

    float *px, *pqkv, *po, *py, *pff, *ppe, *ppool, *pvh, *pch, *ph1;
    cudaGetSymbolAddress((void**)&px,    g_x);
    cudaGetSymbolAddress((void**)&pqkv,  g_qkv);
    cudaGetSymbolAddress((void**)&po,    g_o);
    cudaGetSymbolAddress((void**)&py,    g_y);
    cudaGetSymbolAddress((void**)&pff,   g_ffb);
    cudaGetSymbolAddress((void**)&ppe,   g_pe);
    cudaGetSymbolAddress((void**)&ppool, g_pooled);
    cudaGetSymbolAddress((void**)&pvh,   g_vh);
    cudaGetSymbolAddress((void**)&pch,   g_ch);
    cudaGetSymbolAddress((void**)&ph1,   g_h1);

    pe_kernel<<<SQ, DM>>>(ppe);
    embed_kernel<<<MTOK, DM>>>(board, emb, ppe, px);

    for (int l = 0; l < NL; l++) {
        const float* Wqkv = qkv_w + (size_t)l * 3 * DM * DM;
        const float* Bqkv = qkv_b + (size_t)l * 3 * DM;
        const float* Wout = out_w + (size_t)l * DM * DM;
        const float* Bout = out_b + (size_t)l * DM;
        const float* W1   = ff1_w + (size_t)l * FFD * DM;
        const float* B1   = ff1_b + (size_t)l * FFD;
        const float* W2   = ff2_w + (size_t)l * DM * FFD;
        const float* B2   = ff2_b + (size_t)l * DM;

        sgemm(px, Wqkv, Bqkv, pqkv, MTOK, 3 * DM, DM, 0);
        attn_kernel<<<BATCH * NH, 256>>>(pqkv, po);
        sgemm(po, Wout, Bout, py, MTOK, DM, DM, 0);
        add_ln_kernel<<<MTOK, 256>>>(px, py, ln1_g + l * DM, ln1_b + l * DM);
        sgemm(px, W1, B1, pff, MTOK, FFD, DM, 1);
        sgemm(pff, W2, B2, py, MTOK, DM, FFD, 0);
        add_ln_kernel<<<MTOK, 256>>>(px, py, ln2_g + l * DM, ln2_b + l * DM);
    }

    // heads
    pool_kernel<<<BATCH, DM>>>(px, ppool);

    sgemm(ppool, vw1, vb1, pvh, BATCH, 256, 256, 1);
    head_final_kernel<<<BATCH, 32>>>(pvh, vw2, vb2, out_value, 1, 1);

    sgemm(px, pw1, pb1, ph1, BATCH, 1024, 16384, 1);      // x viewed as [B, 64*256]
    sgemm(ph1, pw2, pb2, out_policy, BATCH, 4096, 1024, 0);

    sgemm(ppool, cw1, cb1, pch, BATCH, 256, 256, 1);
    head_final_kernel<<<BATCH, 32>>>(pch, cw2, cb2, out_class, 3, 0);
}

// round 3
// speedup vs baseline: 2.1324x; 2.1324x over previous
#include <cuda_runtime.h>
#include <cuda_bf16.h>
#include <math.h>
#include <stdint.h>

#define BATCH 4096
#define SQ    64
#define DM    256
#define NH    8
#define HDIM  32
#define FFD   1024
#define NL    6
#define MTOK  (BATCH*SQ)   /* 262144 */

// ---------------- scratch (no allocations allowed) ----------------
__device__ float g_x[MTOK*DM];          // activations [B*64, 256]
__device__ float g_qkv[MTOK*3*DM];      // qkv          [B*64, 768]
__device__ float g_o[MTOK*DM];          // attn output
__device__ float g_y[MTOK*DM];          // sublayer output
__device__ float g_ffb[MTOK*FFD];       // ff hidden
__device__ float g_pe[SQ*DM];
__device__ float g_pooled[BATCH*DM];
__device__ float g_vh[BATCH*DM];
__device__ float g_ch[BATCH*DM];
__device__ float g_h1[BATCH*1024];

// ---------------- PE precompute ----------------
__global__ void pe_kernel(float* __restrict__ pe) {
    int s = blockIdx.x, d = threadIdx.x;
    int row = s >> 3, col = s & 7;
    int m = d >> 1;
    float div = powf(10000.0f, (2.0f * (float)m) / 256.0f);
    float v = (d & 1) ? cosf((float)col / div) : sinf((float)row / div);
    pe[s * DM + d] = v;
}

// ---------------- tokens + embedding + PE ----------------
__global__ void embed_kernel(const float* __restrict__ board,
                             const float* __restrict__ emb,
                             const float* __restrict__ pe,
                             float* __restrict__ x) {
    int tokidx = blockIdx.x;          // b*64 + s
    int b = tokidx >> 6, s = tokidx & 63;
    __shared__ float ch[14];
    __shared__ int tok;
    int d = threadIdx.x;              // 256 threads
    if (d < 14) ch[d] = board[(size_t)b * 896 + (size_t)d * 64 + s];
    __syncthreads();
    if (d == 0) {
        float mx = ch[0]; int idx = 0;
        #pragma unroll
        for (int c = 1; c < 14; c++) { if (ch[c] > mx) { mx = ch[c]; idx = c; } }
        tok = (mx > 0.0f) ? (idx + 1) : 0;
    }
    __syncthreads();
    x[(size_t)tokidx * DM + d] = emb[tok * DM + d] + pe[s * DM + d];
}

// ---------------- bf16 split helpers ----------------
__device__ __forceinline__ void cvt_split2(float x, float y, uint32_t& hi, uint32_t& lo) {
    __nv_bfloat16 hx = __float2bfloat16(x);
    __nv_bfloat16 hy = __float2bfloat16(y);
    __nv_bfloat16 lx = __float2bfloat16(x - __bfloat162float(hx));
    __nv_bfloat16 ly = __float2bfloat16(y - __bfloat162float(hy));
    hi = ((uint32_t)__bfloat16_as_ushort(hy) << 16) | (uint32_t)__bfloat16_as_ushort(hx);
    lo = ((uint32_t)__bfloat16_as_ushort(ly) << 16) | (uint32_t)__bfloat16_as_ushort(lx);
}

__device__ __forceinline__ void mma_bf16(float* c, const uint32_t* a, const uint32_t* b) {
    asm volatile(
        "mma.sync.aligned.m16n8k16.row.col.f32.bf16.bf16.f32 "
        "{%0,%1,%2,%3}, {%4,%5,%6,%7}, {%8,%9}, {%0,%1,%2,%3};\n"
        : "+f"(c[0]), "+f"(c[1]), "+f"(c[2]), "+f"(c[3])
        : "r"(a[0]), "r"(a[1]), "r"(a[2]), "r"(a[3]), "r"(b[0]), "r"(b[1]));
}

// ---------------- bf16x2-split tensor GEMM: C[M,N] = A[M,K] @ W[N,K]^T + bias (+relu)
// BM=BN=128, BK=32, 256 threads = 8 warps, warp tile 64x32 via m16n8k16.
// Error ~2^-18 per product (hi*hi + hi*lo + lo*hi, fp32 accum).
__global__ __launch_bounds__(256, 2) void gemm_bf16x2(
    const float* __restrict__ A, const float* __restrict__ W,
    const float* __restrict__ bias, float* __restrict__ C,
    int M, int N, int K, int relu)
{
    // packed bf16x2 words along k: word w holds k=2w (lo16) and k=2w+1 (hi16).
    // row stride 20 words: (20*grp + tig) mod 32 hits all 32 banks -> conflict-free frag LDS.
    __shared__ uint32_t Ah[128][20];
    __shared__ uint32_t Al[128][20];
    __shared__ uint32_t Wh[128][20];
    __shared__ uint32_t Wl[128][20];

    int tid = threadIdx.x;
    int wid = tid >> 5, lane = tid & 31;
    int grp = lane >> 2, tig = lane & 3;
    int wm = (wid >> 2) * 64;   // warp row offset in tile
    int wn = (wid & 3) * 32;    // warp col offset in tile
    int bm = blockIdx.y * 128, bn = blockIdx.x * 128;

    float acc[4][4][4];
    #pragma unroll
    for (int i = 0; i < 4; i++)
        #pragma unroll
        for (int j = 0; j < 4; j++)
            #pragma unroll
            for (int r = 0; r < 4; r++) acc[i][j][r] = 0.0f;

    const int ldr = tid >> 3;          // 0..31 row group base (with +32*i)
    const int ldw = (tid & 7) << 1;    // word col 0,2,..,14

    for (int k0 = 0; k0 < K; k0 += 32) {
        #pragma unroll
        for (int i = 0; i < 4; i++) {
            int row = ldr + 32 * i;    // 0..127
            const float* ap = A + (size_t)(bm + row) * K + k0 + (ldw << 1);
            const float* wp = W + (size_t)(bn + row) * K + k0 + (ldw << 1);
            float4 av = *(const float4*)ap;
            float4 wv = *(const float4*)wp;
            uint32_t h0, l0, h1, l1;
            cvt_split2(av.x, av.y, h0, l0);
            cvt_split2(av.z, av.w, h1, l1);
            *(uint2*)&Ah[row][ldw] = make_uint2(h0, h1);
            *(uint2*)&Al[row][ldw] = make_uint2(l0, l1);
            cvt_split2(wv.x, wv.y, h0, l0);
            cvt_split2(wv.z, wv.w, h1, l1);
            *(uint2*)&Wh[row][ldw] = make_uint2(h0, h1);
            *(uint2*)&Wl[row][ldw] = make_uint2(l0, l1);
        }
        __syncthreads();

        #pragma unroll
        for (int wb = 0; wb < 16; wb += 8) {   // two k16 chunks per BK=32
            uint32_t ah[4][4], al[4][4];
            #pragma unroll
            for (int mf = 0; mf < 4; mf++) {
                int m = wm + mf * 16 + grp;
                ah[mf][0] = Ah[m][wb + tig];
                ah[mf][1] = Ah[m + 8][wb + tig];
                ah[mf][2] = Ah[m][wb + 4 + tig];
                ah[mf][3] = Ah[m + 8][wb + 4 + tig];
                al[mf][0] = Al[m][wb + tig];
                al[mf][1] = Al[m + 8][wb + tig];
                al[mf][2] = Al[m][wb + 4 + tig];
                al[mf][3] = Al[m + 8][wb + 4 + tig];
            }
            #pragma unroll
            for (int nf = 0; nf < 4; nf++) {
                int n = wn + nf * 8 + grp;
                uint32_t bh[2], bl[2];
                bh[0] = Wh[n][wb + tig];
                bh[1] = Wh[n][wb + 4 + tig];
                bl[0] = Wl[n][wb + tig];
                bl[1] = Wl[n][wb + 4 + tig];
                #pragma unroll
                for (int mf = 0; mf < 4; mf++) {
                    mma_bf16(acc[mf][nf], ah[mf], bh);   // hi*hi
                    mma_bf16(acc[mf][nf], ah[mf], bl);   // hi*lo
                    mma_bf16(acc[mf][nf], al[mf], bh);   // lo*hi
                }
            }
        }
        __syncthreads();
    }

    // epilogue: lane owns cols tig*2, tig*2+1, rows grp / grp+8 per fragment
    #pragma unroll
    for (int mf = 0; mf < 4; mf++) {
        int m = bm + wm + mf * 16 + grp;
        #pragma unroll
        for (int nf = 0; nf < 4; nf++) {
            int n = bn + wn + nf * 8 + tig * 2;
            float b0 = bias ? bias[n] : 0.0f;
            float b1 = bias ? bias[n + 1] : 0.0f;
            float v0 = acc[mf][nf][0] + b0;
            float v1 = acc[mf][nf][1] + b1;
            float v2 = acc[mf][nf][2] + b0;
            float v3 = acc[mf][nf][3] + b1;
            if (relu) {
                v0 = fmaxf(v0, 0.0f); v1 = fmaxf(v1, 0.0f);
                v2 = fmaxf(v2, 0.0f); v3 = fmaxf(v3, 0.0f);
            }
            *(float2*)&C[(size_t)m * N + n]       = make_float2(v0, v1);
            *(float2*)&C[(size_t)(m + 8) * N + n] = make_float2(v2, v3);
        }
    }
}

// ---------------- attention: one CTA per (b, h), register-blocked fp32 ----------------
__global__ __launch_bounds__(256) void attn_kernel(const float* __restrict__ qkv,
                                                   float* __restrict__ o) {
    int bh = blockIdx.x;
    int b = bh >> 3, h = bh & 7;
    __shared__ float qt[32][68];   // [d][i] transposed
    __shared__ float kt[32][68];   // [d][j] transposed
    __shared__ float vsm[64][36];  // [j][d]
    __shared__ float sc[64][68];   // [i][j]
    int tid = threadIdx.x;

    #pragma unroll
    for (int t = tid; t < 512; t += 256) {   // 512 float4 per matrix
        int row = t >> 3, dc = (t & 7) << 2;
        size_t base = ((size_t)b * 64 + row) * 768 + h * 32 + dc;
        float4 qv = *(const float4*)&qkv[base];
        float4 kv = *(const float4*)&qkv[base + 256];
        float4 vv = *(const float4*)&qkv[base + 512];
        qt[dc][row] = qv.x; qt[dc + 1][row] = qv.y; qt[dc + 2][row] = qv.z; qt[dc + 3][row] = qv.w;
        kt[dc][row] = kv.x; kt[dc + 1][row] = kv.y; kt[dc + 2][row] = kv.z; kt[dc + 3][row] = kv.w;
        *(float4*)&vsm[row][dc] = vv;
    }
    __syncthreads();

    {
        int i0 = (tid >> 4) << 2;      // 0..60
        int j0 = (tid & 15) << 2;      // 0..60
        float a[4][4];
        #pragma unroll
        for (int ii = 0; ii < 4; ii++)
            #pragma unroll
            for (int jj = 0; jj < 4; jj++) a[ii][jj] = 0.0f;
        #pragma unroll
        for (int d = 0; d < 32; d++) {
            float4 q4 = *(const float4*)&qt[d][i0];
            float4 k4 = *(const float4*)&kt[d][j0];
            float qv[4] = {q4.x, q4.y, q4.z, q4.w};
            float kv[4] = {k4.x, k4.y, k4.z, k4.w};
            #pragma unroll
            for (int ii = 0; ii < 4; ii++)
                #pragma unroll
                for (int jj = 0; jj < 4; jj++)
                    a[ii][jj] = fmaf(qv[ii], kv[jj], a[ii][jj]);
        }
        const float scale = 0.17677669529663687f;  // 1/sqrt(32)
        #pragma unroll
        for (int ii = 0; ii < 4; ii++) {
            *(float4*)&sc[i0 + ii][j0] = make_float4(a[ii][0] * scale, a[ii][1] * scale,
                                                     a[ii][2] * scale, a[ii][3] * scale);
        }
    }
    __syncthreads();

    {
        int r = tid >> 2;
        int c0 = (tid & 3) << 4;
        float e[16];
        float mx = -1e30f;
        #pragma unroll
        for (int c = 0; c < 16; c++) { e[c] = sc[r][c0 + c]; mx = fmaxf(mx, e[c]); }
        mx = fmaxf(mx, __shfl_xor_sync(0xffffffffu, mx, 1));
        mx = fmaxf(mx, __shfl_xor_sync(0xffffffffu, mx, 2));
        float sum = 0.0f;
        #pragma unroll
        for (int c = 0; c < 16; c++) { e[c] = __expf(e[c] - mx); sum += e[c]; }
        sum += __shfl_xor_sync(0xffffffffu, sum, 1);
        sum += __shfl_xor_sync(0xffffffffu, sum, 2);
        float inv = 1.0f / sum;
        #pragma unroll
        for (int c = 0; c < 16; c++) sc[r][c0 + c] = e[c] * inv;
    }
    __syncthreads();

    {
        int i0 = (tid >> 3) << 1;      // 0..62
        int d0 = (tid & 7) << 2;       // 0..28
        float a0[4] = {0, 0, 0, 0}, a1[4] = {0, 0, 0, 0};
        #pragma unroll 8
        for (int j = 0; j < 64; j++) {
            float s0 = sc[i0][j];
            float s1 = sc[i0 + 1][j];
            float4 v4 = *(const float4*)&vsm[j][d0];
            float vv[4] = {v4.x, v4.y, v4.z, v4.w};
            #pragma unroll
            for (int dd = 0; dd < 4; dd++) {
                a0[dd] = fmaf(s0, vv[dd], a0[dd]);
                a1[dd] = fmaf(s1, vv[dd], a1[dd]);
            }
        }
        size_t ob = ((size_t)b * 64 + i0) * DM + h * 32 + d0;
        *(float4*)&o[ob]      = make_float4(a0[0], a0[1], a0[2], a0[3]);
        *(float4*)&o[ob + DM] = make_float4(a1[0], a1[1], a1[2], a1[3]);
    }
}

// ---------------- residual + layernorm (row-wise) ----------------
__global__ __launch_bounds__(256) void add_ln_kernel(float* __restrict__ x,
                                                     const float* __restrict__ y,
                                                     const float* __restrict__ gg,
                                                     const float* __restrict__ bb) {
    size_t base = (size_t)blockIdx.x * 256;
    int d = threadIdx.x;
    float t = x[base + d] + y[base + d];
    __shared__ float red[8];
    __shared__ float stat;
    float s = t;
    #pragma unroll
    for (int off = 16; off; off >>= 1) s += __shfl_xor_sync(0xffffffffu, s, off);
    if ((d & 31) == 0) red[d >> 5] = s;
    __syncthreads();
    if (d == 0) { float m = 0; for (int i = 0; i < 8; i++) m += red[i]; stat = m * (1.0f / 256.0f); }
    __syncthreads();
    float mean = stat;
    float c = t - mean;
    s = c * c;
    #pragma unroll
    for (int off = 16; off; off >>= 1) s += __shfl_xor_sync(0xffffffffu, s, off);
    __syncthreads();
    if ((d & 31) == 0) red[d >> 5] = s;
    __syncthreads();
    if (d == 0) { float v = 0; for (int i = 0; i < 8; i++) v += red[i]; stat = rsqrtf(v * (1.0f / 256.0f) + 1e-5f); }
    __syncthreads();
    x[base + d] = c * stat * gg[d] + bb[d];
}

// ---------------- mean pooling over the 64 squares ----------------
__global__ void pool_kernel(const float* __restrict__ x, float* __restrict__ pooled) {
    int b = blockIdx.x, d = threadIdx.x;
    float s = 0.0f;
    #pragma unroll 8
    for (int i = 0; i < 64; i++) s += x[((size_t)b * 64 + i) * DM + d];
    pooled[(size_t)b * DM + d] = s * (1.0f / 64.0f);
}

// ---------------- tiny head finals (value / classification) ----------------
__global__ void head_final_kernel(const float* __restrict__ hid,
                                  const float* __restrict__ w,
                                  const float* __restrict__ bias,
                                  float* __restrict__ out, int nout, int do_tanh) {
    int b = blockIdx.x;
    int lane = threadIdx.x;  // 32 threads
    for (int o = 0; o < nout; o++) {
        float s = 0.0f;
        #pragma unroll
        for (int i = lane; i < 256; i += 32) s = fmaf(hid[(size_t)b * 256 + i], w[o * 256 + i], s);
        #pragma unroll
        for (int off = 16; off; off >>= 1) s += __shfl_xor_sync(0xffffffffu, s, off);
        if (lane == 0) {
            float v = s + bias[o];
            out[(size_t)b * nout + o] = do_tanh ? tanhf(v) : v;
        }
    }
}

// ---------------- host side ----------------
static inline void sgemm(const float* A, const float* W, const float* bias, float* C,
                         int M, int N, int K, int relu) {
    dim3 g(N / 128, M / 128), blk(256);
    gemm_bf16x2<<<g, blk>>>(A, W, bias, C, M, N, K, relu);
}

extern "C" void kernel_launch(void* const* d_in, const int* in_sizes, int n_in,
                              void* d_out, int out_size) {
    const float* board = (const float*)d_in[0];
    const float* emb   = (const float*)d_in[1];
    const float* qkv_w = (const float*)d_in[2];
    const float* qkv_b = (const float*)d_in[3];
    const float* out_w = (const float*)d_in[4];
    const float* out_b = (const float*)d_in[5];
    const float* ln1_g = (const float*)d_in[6];
    const float* ln1_b = (const float*)d_in[7];
    const float* ln2_g = (const float*)d_in[8];
    const float* ln2_b = (const float*)d_in[9];
    const float* ff1_w = (const float*)d_in[10];
    const float* ff1_b = (const float*)d_in[11];
    const float* ff2_w = (const float*)d_in[12];
    const float* ff2_b = (const float*)d_in[13];
    const float* vw1 = (const float*)d_in[14];
    const float* vb1 = (const float*)d_in[15];
    const float* vw2 = (const float*)d_in[16];
    const float* vb2 = (const float*)d_in[17];
    const float* pw1 = (const float*)d_in[18];
    const float* pb1 = (const float*)d_in[19];
    const float* pw2 = (const float*)d_in[20];
    const float* pb2 = (const float*)d_in[21];
    const float* cw1 = (const float*)d_in[22];
    const float* cb1 = (const float*)d_in[23];
    const float* cw2 = (const float*)d_in[24];
    const float* cb2 = (const float*)d_in[25];

    float* out = (float*)d_out;
    float* out_value  = out;                                  // [4096, 1]
    float* out_policy = out + BATCH;                          // [4096, 4096]
    float* out_class  = out + BATCH + (size_t)BATCH * 4096;   // [4096, 3]

    float *px, *pqkv, *po, *py, *pff, *ppe, *ppool, *pvh, *pch, *ph1;
    cudaGetSymbolAddress((void**)&px,    g_x);
    cudaGetSymbolAddress((void**)&pqkv,  g_qkv);
    cudaGetSymbolAddress((void**)&po,    g_o);
    cudaGetSymbolAddress((void**)&py,    g_y);
    cudaGetSymbolAddress((void**)&pff,   g_ffb);
    cudaGetSymbolAddress((void**)&ppe,   g_pe);
    cudaGetSymbolAddress((void**)&ppool, g_pooled);
    cudaGetSymbolAddress((void**)&pvh,   g_vh);
    cudaGetSymbolAddress((void**)&pch,   g_ch);
    cudaGetSymbolAddress((void**)&ph1,   g_h1);

    pe_kernel<<<SQ, DM>>>(ppe);
    embed_kernel<<<MTOK, DM>>>(board, emb, ppe, px);

    for (int l = 0; l < NL; l++) {
        const float* Wqkv = qkv_w + (size_t)l * 3 * DM * DM;
        const float* Bqkv = qkv_b + (size_t)l * 3 * DM;
        const float* Wout = out_w + (size_t)l * DM * DM;
        const float* Bout = out_b + (size_t)l * DM;
        const float* W1   = ff1_w + (size_t)l * FFD * DM;
        const float* B1   = ff1_b + (size_t)l * FFD;
        const float* W2   = ff2_w + (size_t)l * DM * FFD;
        const float* B2   = ff2_b + (size_t)l * DM;

        sgemm(px, Wqkv, Bqkv, pqkv, MTOK, 3 * DM, DM, 0);
        attn_kernel<<<BATCH * NH, 256>>>(pqkv, po);
        sgemm(po, Wout, Bout, py, MTOK, DM, DM, 0);
        add_ln_kernel<<<MTOK, 256>>>(px, py, ln1_g + l * DM, ln1_b + l * DM);
        sgemm(px, W1, B1, pff, MTOK, FFD, DM, 1);
        sgemm(pff, W2, B2, py, MTOK, DM, FFD, 0);
        add_ln_kernel<<<MTOK, 256>>>(px, py, ln2_g + l * DM, ln2_b + l * DM);
    }

    // heads
    pool_kernel<<<BATCH, DM>>>(px, ppool);

    sgemm(ppool, vw1, vb1, pvh, BATCH, 256, 256, 1);
    head_final_kernel<<<BATCH, 32>>>(pvh, vw2, vb2, out_value, 1, 1);

    sgemm(px, pw1, pb1, ph1, BATCH, 1024, 16384, 1);      // x viewed as [B, 64*256]
    sgemm(ph1, pw2, pb2, out_policy, BATCH, 4096, 1024, 0);

    sgemm(ppool, cw1, cb1, pch, BATCH, 256, 256, 1);
    head_final_kernel<<<BATCH, 32>>>(pch, cw2, cb2, out_class, 3, 0);
}